// round 13
// baseline (speedup 1.0000x reference)
#include <cuda_runtime.h>
#include <cuda_bf16.h>
#include <math.h>

#define NN 50000
#define EE 800000
#define GG 64
#define ETOT (EE + NN)
#define SCHUNK 512

typedef unsigned long long ull;
typedef unsigned int u32;
typedef unsigned short u16;

// ---------------- static device scratch ----------------
__device__ float g_XL[NN * 128];
__device__ float g_XR[NN * 128];
__device__ float g_BA[NN * 128];
__device__ float g_BB[NN * 128];
__device__ int   g_rowptr[NN + 1];
__device__ int   g_tmp[NN];          // degree counts (re-zeroed each call), then cursors
__device__ int   g_lscan[NN];
__device__ int   g_bsum[256];
__device__ int   g_col[ETOT];
__device__ float g_cnt[GG];
__device__ u32   g_poolctr;
__device__ u16   g_Bhi0[256 * 128];
__device__ u16   g_Blo0[256 * 128];
__device__ u16   g_Bhi1[256 * 128];
__device__ u16   g_Blo1[256 * 128];
__device__ u16   g_Bhi2[128 * 128];
__device__ u16   g_Blo2[128 * 128];

// ---------------- helpers ----------------
__device__ __forceinline__ u32 smem_u32(const void* p) {
    u32 a;
    asm("{ .reg .u64 t; cvta.to.shared.u64 t, %1; cvt.u32.u64 %0, t; }" : "=r"(a) : "l"(p));
    return a;
}

__device__ __forceinline__ u32 pack_bf16x2(float lo, float hi) {
    u32 r;
    asm("cvt.rn.bf16x2.f32 %0, %1, %2;" : "=r"(r) : "f"(hi), "f"(lo));
    return r;
}

__device__ __forceinline__ u32 swz_off(int r, int k) {
    int chunk = k >> 3;
    return (u32)(r * 256 + (((chunk ^ (r & 7)) & 15) << 4) + (k & 7) * 2);
}

__device__ __forceinline__ void ldmx4(u32& r0, u32& r1, u32& r2, u32& r3, u32 addr) {
    asm volatile("ldmatrix.sync.aligned.m8n8.x4.shared.b16 {%0,%1,%2,%3}, [%4];"
                 : "=r"(r0), "=r"(r1), "=r"(r2), "=r"(r3) : "r"(addr));
}

__device__ __forceinline__ void mma_bf16(float* c, const u32* a, const u32* b) {
    asm volatile("mma.sync.aligned.m16n8k16.row.col.f32.bf16.bf16.f32 "
                 "{%0,%1,%2,%3}, {%4,%5,%6,%7}, {%8,%9}, {%0,%1,%2,%3};"
                 : "+f"(c[0]), "+f"(c[1]), "+f"(c[2]), "+f"(c[3])
                 : "r"(a[0]), "r"(a[1]), "r"(a[2]), "r"(a[3]), "r"(b[0]), "r"(b[1]));
}

__device__ __forceinline__ void cp16(u32 s, const void* g) {
    asm volatile("{ .reg .u64 t; cvta.to.global.u64 t, %1; "
                 "cp.async.cg.shared.global [%0], [t], 16; }" :: "r"(s), "l"(g));
}
#define CP_COMMIT() asm volatile("cp.async.commit_group;" ::: "memory")
#define CP_WAIT0()  asm volatile("cp.async.wait_group 0;" ::: "memory")

// ---------------- weight prep ----------------
__device__ __forceinline__ void prep_one(const float* __restrict__ Wl,
                                         const float* __restrict__ Wr,
                                         u16* __restrict__ Bhi, u16* __restrict__ Blo,
                                         int M, int i) {
    int r = i >> 7, k = i & 127;
    float v = (r < M) ? Wl[k * M + r] : Wr[k * M + r - M];
    __nv_bfloat16 h = __float2bfloat16(v);
    float hf = __bfloat162float(h);
    __nv_bfloat16 l = __float2bfloat16(v - hf);
    u32 off = swz_off(r, k) >> 1;
    Bhi[off] = *(u16*)&h;
    Blo[off] = *(u16*)&l;
}

__global__ void k_prep0(const float* Wl0, const float* Wr0, u16* Bhi0, u16* Blo0) {
    int i = blockIdx.x * blockDim.x + threadIdx.x;
    if (i < 32768) prep_one(Wl0, Wr0, Bhi0, Blo0, 128, i);
}

__global__ void k_prep12(const float* Wl1, const float* Wr1,
                         const float* Wl2, const float* Wr2,
                         u16* Bhi1, u16* Blo1, u16* Bhi2, u16* Blo2) {
    int i = blockIdx.x * blockDim.x + threadIdx.x;
    if (i < 32768)      prep_one(Wl1, Wr1, Bhi1, Blo1, 128, i);
    else if (i < 49152) prep_one(Wl2, Wr2, Bhi2, Blo2, 64, i - 32768);
}

// ---------------- HMMA dual GEMM: 64 rows x 128 cols, warp tile 16x64 ----------------
#define SB_HI 0
#define SB_LO 32768
#define GSMEM 65536

__global__ __launch_bounds__(256, 2)
void k_gemm_hmma(const float* __restrict__ X, const u16* __restrict__ Bimg_hi,
                 const u16* __restrict__ Bimg_lo, float* __restrict__ XL,
                 float* __restrict__ XR, int n, int M) {
    extern __shared__ char smem[];
    const u32 sb = smem_u32(smem);
    const int tid = threadIdx.x, wid = tid >> 5, lane = tid & 31;
    const int row0 = blockIdx.x * 64;
    const int cb0 = blockIdx.y * 128;

    {
        const char* bh = (const char*)(Bimg_hi + (size_t)cb0 * 128);
        const char* bl = (const char*)(Bimg_lo + (size_t)cb0 * 128);
        for (int i = tid * 16; i < 32768; i += 256 * 16) {
            cp16(sb + SB_HI + i, bh + i);
            cp16(sb + SB_LO + i, bl + i);
        }
        CP_COMMIT();
    }

    const int warp_m = wid & 3;
    const int warp_n = wid >> 2;
    const int gr = row0 + warp_m * 16 + (lane >> 2);
    const bool ok0 = gr < n, ok1 = gr + 8 < n;
    const float* Xr0 = X + (size_t)gr * 128 + (lane & 3) * 2;
    const float* Xr1 = Xr0 + 8 * 128;
    const int nrowb = warp_n * 64 + ((lane >> 4) & 1) * 8 + (lane & 7);
    const int bkh = (lane >> 3) & 1;

    float acc[8][4];
#pragma unroll
    for (int j = 0; j < 8; j++)
#pragma unroll
        for (int c = 0; c < 4; c++) acc[j][c] = 0.f;

    float2 raw[4];
    raw[0] = ok0 ? *(const float2*)Xr0 : make_float2(0.f, 0.f);
    raw[1] = ok1 ? *(const float2*)Xr1 : make_float2(0.f, 0.f);
    raw[2] = ok0 ? *(const float2*)(Xr0 + 8) : make_float2(0.f, 0.f);
    raw[3] = ok1 ? *(const float2*)(Xr1 + 8) : make_float2(0.f, 0.f);

    CP_WAIT0();
    __syncthreads();

#pragma unroll
    for (int ks = 0; ks < 8; ks++) {
        float2 nxt[4];
        if (ks < 7) {
            const float* p0 = Xr0 + (ks + 1) * 16;
            const float* p1 = Xr1 + (ks + 1) * 16;
            nxt[0] = ok0 ? *(const float2*)p0 : make_float2(0.f, 0.f);
            nxt[1] = ok1 ? *(const float2*)p1 : make_float2(0.f, 0.f);
            nxt[2] = ok0 ? *(const float2*)(p0 + 8) : make_float2(0.f, 0.f);
            nxt[3] = ok1 ? *(const float2*)(p1 + 8) : make_float2(0.f, 0.f);
        }
        u32 ahi[4], alo[4];
#pragma unroll
        for (int q = 0; q < 4; q++) {
            u32 h = pack_bf16x2(raw[q].x, raw[q].y);
            ahi[q] = h;
            float h0 = __uint_as_float(h << 16);
            float h1 = __uint_as_float(h & 0xffff0000u);
            alo[q] = pack_bf16x2(raw[q].x - h0, raw[q].y - h1);
        }
#pragma unroll
        for (int jj = 0; jj < 4; jj++) {
            int r = nrowb + jj * 16;
            u32 off = (u32)(r * 256 + ((((ks * 2 + bkh) ^ (r & 7)) & 15) << 4));
            u32 bh[4], bl[4];
            ldmx4(bh[0], bh[1], bh[2], bh[3], sb + SB_HI + off);
            ldmx4(bl[0], bl[1], bl[2], bl[3], sb + SB_LO + off);
            mma_bf16(acc[jj * 2], ahi, bh);
            mma_bf16(acc[jj * 2], alo, bh);
            mma_bf16(acc[jj * 2], ahi, bl);
            mma_bf16(acc[jj * 2 + 1], ahi, bh + 2);
            mma_bf16(acc[jj * 2 + 1], alo, bh + 2);
            mma_bf16(acc[jj * 2 + 1], ahi, bl + 2);
        }
#pragma unroll
        for (int q = 0; q < 4; q++) raw[q] = nxt[q];
    }

    const int cwb = cb0 + warp_n * 64;
    float* OUT = (cwb < M) ? XL : XR;
    const int cof = (cwb < M) ? cwb : cwb - M;
    const int r0 = row0 + warp_m * 16 + (lane >> 2);
#pragma unroll
    for (int j = 0; j < 8; j++) {
        int c = cof + j * 8 + (lane & 3) * 2;
        if (r0 < n)
            *(float2*)&OUT[(size_t)r0 * M + c] = make_float2(acc[j][0], acc[j][1]);
        if (r0 + 8 < n)
            *(float2*)&OUT[(size_t)(r0 + 8) * M + c] = make_float2(acc[j][2], acc[j][3]);
    }
}

// ---------------- CSR build ----------------
__global__ void k_hist(const int* __restrict__ tgt, int* cnt, int e) {
    int i = blockIdx.x * blockDim.x + threadIdx.x;
    if (i < e) atomicAdd(&cnt[tgt[i]], 1);
}

__global__ void k_scanA(const int* __restrict__ counts, int* __restrict__ lscan,
                        int* __restrict__ bsum, int n) {
    __shared__ int wsum[16];
    const int tid = threadIdx.x, lane = tid & 31, wid = tid >> 5;
    const int i = blockIdx.x * SCHUNK + tid;
    int v = (i < n) ? (counts[i] + 1) : 0;
    int incl = v;
#pragma unroll
    for (int off = 1; off < 32; off <<= 1) {
        int t = __shfl_up_sync(0xffffffffu, incl, off);
        if (lane >= off) incl += t;
    }
    if (lane == 31) wsum[wid] = incl;
    __syncthreads();
    if (tid < 16) {
        int w = wsum[tid];
        int s = w;
#pragma unroll
        for (int off = 1; off < 16; off <<= 1) {
            int t = __shfl_up_sync(0xffffu, s, off);
            if (tid >= off) s += t;
        }
        wsum[tid] = s - w;
    }
    __syncthreads();
    incl += wsum[wid];
    if (i < n) lscan[i] = incl;
    if (tid == SCHUNK - 1) bsum[blockIdx.x] = incl;
}

__global__ void k_scanB(int* bsum, int nb, float* out, float* gcnt) {
    if (blockIdx.x == 0) {
        __shared__ int wsum[4];
        const int tid = threadIdx.x, lane = tid & 31, wid = tid >> 5;
        if (tid < 128) {
            int v = (tid < nb) ? bsum[tid] : 0;
            int incl = v;
#pragma unroll
            for (int off = 1; off < 32; off <<= 1) {
                int t = __shfl_up_sync(0xffffffffu, incl, off);
                if (lane >= off) incl += t;
            }
            if (lane == 31) wsum[wid] = incl;
            __syncthreads();
            int base = 0;
            for (int w = 0; w < wid; w++) base += wsum[w];
            if (tid < nb) bsum[tid] = base + incl - v;
        }
    } else {
        int i = (blockIdx.x - 1) * 256 + threadIdx.x;
        if (i < GG * 64) out[i] = 0.f;
        if (i < GG) gcnt[i] = 0.f;
    }
}

__global__ void k_scanC(const int* __restrict__ counts, int* __restrict__ cursor,
                        const int* __restrict__ lscan, const int* __restrict__ bsum,
                        int* __restrict__ rowptr, int n) {
    int i = blockIdx.x * blockDim.x + threadIdx.x;
    if (i < n) {
        int incl = bsum[i / SCHUNK] + lscan[i];
        rowptr[i + 1] = incl;
        cursor[i] = incl - (counts[i] + 1);
    }
    if (i == 0) rowptr[0] = 0;
}

__global__ void k_scatter(const int* __restrict__ src, const int* __restrict__ tgt,
                          int* wcur, int* col, int e, int n) {
    int i = blockIdx.x * blockDim.x + threadIdx.x;
    if (i < e) {
        int d = tgt[i];
        int p = atomicAdd(&wcur[d], 1);
        col[p] = src[i];
    } else if (i < e + n) {
        int v = i - e;
        int p = atomicAdd(&wcur[v], 1);
        col[p] = v;
    }
}

__global__ void k_zcnt(int* cnt, int n) {
    int i = blockIdx.x * blockDim.x + threadIdx.x;
    if (i < n) cnt[i] = 0;
}

// ---------------- GATv2 aggregation: 2 edges per warp iteration (half-warp/edge) ----
// LPE=16 lanes per edge; V = HC/16 features per lane. Fixed-reference softmax.
template <int V>
__device__ __forceinline__ void ldrowV(float* d, const float* p) {
    if (V == 8) {
        float4 a = *(const float4*)p;
        float4 b = *(const float4*)(p + 4);
        d[0]=a.x; d[1]=a.y; d[2]=a.z; d[3]=a.w;
        d[4]=b.x; d[5]=b.y; d[6]=b.z; d[7]=b.w;
    } else {
        float4 a = *(const float4*)p;
        d[0]=a.x; d[1]=a.y; d[2]=a.z; d[3]=a.w;
    }
}

template <int HC, int H>
__global__ void k_gat(const float* __restrict__ XL, const float* __restrict__ XR,
                      const int* __restrict__ rowptr, const int* __restrict__ col,
                      const float* __restrict__ att, const float* __restrict__ bias,
                      float* __restrict__ Y, int n) {
    constexpr int V  = HC / 16;     // 8 (HC=128) or 4 (HC=64)
    constexpr int GW = 16 / H;      // lanes per head group within a half (4 or 16)
    const int lane = threadIdx.x & 31;
    const int half = lane >> 4;     // which edge of the pair
    const int hl   = lane & 15;     // lane within half
    const int node = blockIdx.x * (blockDim.x >> 5) + (threadIdx.x >> 5);
    if (node >= n) return;

    float attv[V], bv[V], xr[V], acc[V];
#pragma unroll
    for (int v = 0; v < V; v++) {
        attv[v] = att[hl * V + v];
        bv[v]   = bias[hl * V + v];
        acc[v]  = 0.f;
    }
    ldrowV<V>(xr, XR + (size_t)node * HC + hl * V);

    const int e0 = rowptr[node], e1 = rowptr[node + 1];
    const int elast = e1 - 1;
    float den = 0.f;

    float nb[V];
    ldrowV<V>(nb, XL + (size_t)__ldg(&col[min(e0 + half, elast)]) * HC + hl * V);

    for (int e = e0; e < e1; e += 2) {
        float xl[V];
#pragma unroll
        for (int v = 0; v < V; v++) xl[v] = nb[v];
        // prefetch next pair (clamped)
        ldrowV<V>(nb, XL + (size_t)__ldg(&col[min(e + 2 + half, elast)]) * HC + hl * V);

        float s = 0.f;
#pragma unroll
        for (int v = 0; v < V; v++) {
            float t = xl[v] + xr[v];
            t = fmaxf(t, 0.2f * t);   // leaky relu
            s = fmaf(attv[v], t, s);
        }
#pragma unroll
        for (int off = GW >> 1; off > 0; off >>= 1)
            s += __shfl_xor_sync(0xffffffffu, s, off);

        float w = ((e + half) < e1) ? __expf(s) : 0.f;
        den += w;
#pragma unroll
        for (int v = 0; v < V; v++) acc[v] = fmaf(w, xl[v], acc[v]);
    }

    // merge the two halves
    den += __shfl_xor_sync(0xffffffffu, den, 16);
#pragma unroll
    for (int v = 0; v < V; v++) acc[v] += __shfl_xor_sync(0xffffffffu, acc[v], 16);

    float inv = 1.f / den;
    // each half writes V/2 features: half 0 -> [0,V/2), half 1 -> [V/2,V)
    float* yp = Y + (size_t)node * HC + hl * V + half * (V / 2);
    if (V == 8) {
        float4 o;
        float y0 = fmaf(acc[half * 4 + 0], inv, bv[half * 4 + 0]);
        float y1 = fmaf(acc[half * 4 + 1], inv, bv[half * 4 + 1]);
        float y2 = fmaf(acc[half * 4 + 2], inv, bv[half * 4 + 2]);
        float y3 = fmaf(acc[half * 4 + 3], inv, bv[half * 4 + 3]);
        o.x = fmaxf(y0, 0.2f * y0);
        o.y = fmaxf(y1, 0.2f * y1);
        o.z = fmaxf(y2, 0.2f * y2);
        o.w = fmaxf(y3, 0.2f * y3);
        *(float4*)yp = o;
    } else {
        float2 o;
        float y0 = fmaf(acc[half * 2 + 0], inv, bv[half * 2 + 0]);
        float y1 = fmaf(acc[half * 2 + 1], inv, bv[half * 2 + 1]);
        o.x = fmaxf(y0, 0.2f * y0);
        o.y = fmaxf(y1, 0.2f * y1);
        *(float2*)yp = o;
    }
}

// ---------------- global mean pool with fused finalize ----------------
#define PCH 256
__global__ void k_pool2(const float* __restrict__ X, const int* __restrict__ batch,
                        float* out, float* cnt, int n) {
    __shared__ bool s_last;
    const int f = threadIdx.x;
    const int chunk = blockIdx.x * blockDim.y + threadIdx.y;
    const int n0 = chunk * PCH;
    if (n0 < n) {
        const int n1 = min(n, n0 + PCH);
        int curg = __ldg(&batch[n0]);
        float acc = 0.f, c = 0.f;
        for (int node = n0; node < n1; node++) {
            int g = __ldg(&batch[node]);
            if (g != curg) {
                atomicAdd(&out[curg * 64 + f], acc);
                if (f == 0) atomicAdd(&cnt[curg], c);
                acc = 0.f; c = 0.f; curg = g;
            }
            acc += X[(size_t)node * 64 + f];
            c += 1.f;
        }
        atomicAdd(&out[curg * 64 + f], acc);
        if (f == 0) atomicAdd(&cnt[curg], c);
    }
    __threadfence();
    __syncthreads();
    const int tid = threadIdx.y * 64 + threadIdx.x;
    if (tid == 0) {
        u32 t = atomicAdd(&g_poolctr, 1u);
        s_last = (t == gridDim.x - 1);
    }
    __syncthreads();
    if (s_last) {
        for (int i = tid; i < GG * 64; i += 256)
            out[i] /= fmaxf(cnt[i >> 6], 1.f);
        if (tid == 0) g_poolctr = 0;
    }
}

// ---------------- launch ----------------
extern "C" void kernel_launch(void* const* d_in, const int* in_sizes, int n_in,
                              void* d_out, int out_size) {
    const float* x     = (const float*)d_in[0];
    const int*   ei    = (const int*)d_in[1];
    const int*   batch = (const int*)d_in[2];
    const float* Wl0 = (const float*)d_in[3];
    const float* Wr0 = (const float*)d_in[4];
    const float* at0 = (const float*)d_in[5];
    const float* b0  = (const float*)d_in[6];
    const float* Wl1 = (const float*)d_in[7];
    const float* Wr1 = (const float*)d_in[8];
    const float* at1 = (const float*)d_in[9];
    const float* b1  = (const float*)d_in[10];
    const float* Wl2 = (const float*)d_in[11];
    const float* Wr2 = (const float*)d_in[12];
    const float* at2 = (const float*)d_in[13];
    const float* b2  = (const float*)d_in[14];
    float* out = (float*)d_out;

    const int n = in_sizes[2];
    const int e = in_sizes[1] / 2;
    const int* src = ei;
    const int* tgt = ei + e;

    float *pXL, *pXR, *pBA, *pBB, *pcnt;
    int *prow, *ptmp, *pcol, *plscan, *pbsum;
    u16 *pBhi0, *pBlo0, *pBhi1, *pBlo1, *pBhi2, *pBlo2;
    cudaGetSymbolAddress((void**)&pXL, g_XL);
    cudaGetSymbolAddress((void**)&pXR, g_XR);
    cudaGetSymbolAddress((void**)&pBA, g_BA);
    cudaGetSymbolAddress((void**)&pBB, g_BB);
    cudaGetSymbolAddress((void**)&prow, g_rowptr);
    cudaGetSymbolAddress((void**)&ptmp, g_tmp);
    cudaGetSymbolAddress((void**)&pcol, g_col);
    cudaGetSymbolAddress((void**)&plscan, g_lscan);
    cudaGetSymbolAddress((void**)&pbsum, g_bsum);
    cudaGetSymbolAddress((void**)&pcnt, g_cnt);
    cudaGetSymbolAddress((void**)&pBhi0, g_Bhi0);
    cudaGetSymbolAddress((void**)&pBlo0, g_Blo0);
    cudaGetSymbolAddress((void**)&pBhi1, g_Bhi1);
    cudaGetSymbolAddress((void**)&pBlo1, g_Blo1);
    cudaGetSymbolAddress((void**)&pBhi2, g_Bhi2);
    cudaGetSymbolAddress((void**)&pBlo2, g_Blo2);

    cudaFuncSetAttribute(k_gemm_hmma, cudaFuncAttributeMaxDynamicSharedMemorySize, GSMEM);

    const int gx      = (n + 63) / 64;
    const int ablocks = (n + 7) / 8;
    const int nsb     = (n + SCHUNK - 1) / SCHUNK;

    cudaStream_t s;
    cudaStreamCreateWithFlags(&s, cudaStreamNonBlocking);
    cudaEvent_t eFork, eJoin;
    cudaEventCreateWithFlags(&eFork, cudaEventDisableTiming);
    cudaEventCreateWithFlags(&eJoin, cudaEventDisableTiming);

    cudaEventRecord(eFork, 0);
    cudaStreamWaitEvent(s, eFork, 0);

    // ---- side stream: prep for layers 1/2 + CSR build + pool-buffer zeroing
    k_prep12<<<192, 256, 0, s>>>(Wl1, Wr1, Wl2, Wr2, pBhi1, pBlo1, pBhi2, pBlo2);
    k_hist<<<(e + 255) / 256, 256, 0, s>>>(tgt, ptmp, e);
    k_scanA<<<nsb, SCHUNK, 0, s>>>(ptmp, plscan, pbsum, n);
    k_scanB<<<1 + (GG * 64 + 255) / 256, 256, 0, s>>>(pbsum, nsb, out, pcnt);
    k_scanC<<<(n + 255) / 256, 256, 0, s>>>(ptmp, ptmp, plscan, pbsum, prow, n);
    k_scatter<<<(e + n + 255) / 256, 256, 0, s>>>(src, tgt, ptmp, pcol, e, n);
    k_zcnt<<<(n + 255) / 256, 256, 0, s>>>(ptmp, n);
    cudaEventRecord(eJoin, s);

    // ---- main stream: layer-0 prep + GEMM
    k_prep0<<<128, 256>>>(Wl0, Wr0, pBhi0, pBlo0);
    k_gemm_hmma<<<dim3(gx, 2), 256, GSMEM>>>(x, pBhi0, pBlo0, pXL, pXR, n, 128);

    cudaStreamWaitEvent(0, eJoin, 0);

    // layer 0 aggregate
    k_gat<128, 4><<<ablocks, 256>>>(pXL, pXR, prow, pcol, at0, b0, pBA, n);

    // layer 1
    k_gemm_hmma<<<dim3(gx, 2), 256, GSMEM>>>(pBA, pBhi1, pBlo1, pXL, pXR, n, 128);
    k_gat<128, 4><<<ablocks, 256>>>(pXL, pXR, prow, pcol, at1, b1, pBB, n);

    // layer 2 (1 head x 64)
    k_gemm_hmma<<<dim3(gx, 1), 256, GSMEM>>>(pBB, pBhi2, pBlo2, pXL, pXR, n, 64);
    k_gat<64, 1><<<ablocks, 256>>>(pXL, pXR, prow, pcol, at2, b2, pBA, n);

    // global mean pool (finalize fused)
    {
        dim3 blk(64, 4);
        int pblocks = (n + PCH * 4 - 1) / (PCH * 4);
        k_pool2<<<pblocks, blk>>>(pBA, batch, out, pcnt, n);
    }
}

// round 14
// speedup vs baseline: 1.0590x; 1.0590x over previous
#include <cuda_runtime.h>
#include <cuda_bf16.h>
#include <math.h>

#define NN 50000
#define EE 800000
#define GG 64
#define ETOT (EE + NN)
#define SCHUNK 512

typedef unsigned long long ull;
typedef unsigned int u32;
typedef unsigned short u16;

// ---------------- static device scratch ----------------
__device__ float g_XL[NN * 128];
__device__ float g_XR[NN * 128];
__device__ float g_BA[NN * 128];
__device__ float g_BB[NN * 128];
__device__ int   g_rowptr[NN + 1];
__device__ int   g_tmp[NN];
__device__ int   g_lscan[NN];
__device__ int   g_bsum[256];
__device__ int   g_col[ETOT];
__device__ float g_cnt[GG];
__device__ u32   g_poolctr;
__device__ u16   g_Bhi0[256 * 128];
__device__ u16   g_Blo0[256 * 128];
__device__ u16   g_Bhi1[256 * 128];
__device__ u16   g_Blo1[256 * 128];
__device__ u16   g_Bhi2[128 * 128];
__device__ u16   g_Blo2[128 * 128];

// ---------------- helpers ----------------
__device__ __forceinline__ u32 smem_u32(const void* p) {
    u32 a;
    asm("{ .reg .u64 t; cvta.to.shared.u64 t, %1; cvt.u32.u64 %0, t; }" : "=r"(a) : "l"(p));
    return a;
}

__device__ __forceinline__ u32 pack_bf16x2(float lo, float hi) {
    u32 r;
    asm("cvt.rn.bf16x2.f32 %0, %1, %2;" : "=r"(r) : "f"(hi), "f"(lo));
    return r;
}

__device__ __forceinline__ u32 swz_off(int r, int k) {
    int chunk = k >> 3;
    return (u32)(r * 256 + (((chunk ^ (r & 7)) & 15) << 4) + (k & 7) * 2);
}

__device__ __forceinline__ void ldmx4(u32& r0, u32& r1, u32& r2, u32& r3, u32 addr) {
    asm volatile("ldmatrix.sync.aligned.m8n8.x4.shared.b16 {%0,%1,%2,%3}, [%4];"
                 : "=r"(r0), "=r"(r1), "=r"(r2), "=r"(r3) : "r"(addr));
}

__device__ __forceinline__ void mma_bf16(float* c, const u32* a, const u32* b) {
    asm volatile("mma.sync.aligned.m16n8k16.row.col.f32.bf16.bf16.f32 "
                 "{%0,%1,%2,%3}, {%4,%5,%6,%7}, {%8,%9}, {%0,%1,%2,%3};"
                 : "+f"(c[0]), "+f"(c[1]), "+f"(c[2]), "+f"(c[3])
                 : "r"(a[0]), "r"(a[1]), "r"(a[2]), "r"(a[3]), "r"(b[0]), "r"(b[1]));
}

__device__ __forceinline__ void cp16(u32 s, const void* g) {
    asm volatile("{ .reg .u64 t; cvta.to.global.u64 t, %1; "
                 "cp.async.cg.shared.global [%0], [t], 16; }" :: "r"(s), "l"(g));
}
#define CP_COMMIT() asm volatile("cp.async.commit_group;" ::: "memory")
#define CP_WAIT0()  asm volatile("cp.async.wait_group 0;" ::: "memory")

// ---------------- weight prep ----------------
__device__ __forceinline__ void prep_one(const float* __restrict__ Wl,
                                         const float* __restrict__ Wr,
                                         u16* __restrict__ Bhi, u16* __restrict__ Blo,
                                         int M, int i) {
    int r = i >> 7, k = i & 127;
    float v = (r < M) ? Wl[k * M + r] : Wr[k * M + r - M];
    __nv_bfloat16 h = __float2bfloat16(v);
    float hf = __bfloat162float(h);
    __nv_bfloat16 l = __float2bfloat16(v - hf);
    u32 off = swz_off(r, k) >> 1;
    Bhi[off] = *(u16*)&h;
    Blo[off] = *(u16*)&l;
}

__global__ void k_prep0(const float* Wl0, const float* Wr0, u16* Bhi0, u16* Blo0) {
    int i = blockIdx.x * blockDim.x + threadIdx.x;
    if (i < 32768) prep_one(Wl0, Wr0, Bhi0, Blo0, 128, i);
}

__global__ void k_prep12(const float* Wl1, const float* Wr1,
                         const float* Wl2, const float* Wr2,
                         u16* Bhi1, u16* Blo1, u16* Bhi2, u16* Blo2) {
    int i = blockIdx.x * blockDim.x + threadIdx.x;
    if (i < 32768)      prep_one(Wl1, Wr1, Bhi1, Blo1, 128, i);
    else if (i < 49152) prep_one(Wl2, Wr2, Bhi2, Blo2, 64, i - 32768);
}

// ---------------- HMMA dual GEMM: 64 rows x 128 cols, warp tile 16x64 ----------------
#define SB_HI 0
#define SB_LO 32768
#define GSMEM 65536

__global__ __launch_bounds__(256, 2)
void k_gemm_hmma(const float* __restrict__ X, const u16* __restrict__ Bimg_hi,
                 const u16* __restrict__ Bimg_lo, float* __restrict__ XL,
                 float* __restrict__ XR, int n, int M) {
    extern __shared__ char smem[];
    const u32 sb = smem_u32(smem);
    const int tid = threadIdx.x, wid = tid >> 5, lane = tid & 31;
    const int row0 = blockIdx.x * 64;
    const int cb0 = blockIdx.y * 128;

    {
        const char* bh = (const char*)(Bimg_hi + (size_t)cb0 * 128);
        const char* bl = (const char*)(Bimg_lo + (size_t)cb0 * 128);
        for (int i = tid * 16; i < 32768; i += 256 * 16) {
            cp16(sb + SB_HI + i, bh + i);
            cp16(sb + SB_LO + i, bl + i);
        }
        CP_COMMIT();
    }

    const int warp_m = wid & 3;
    const int warp_n = wid >> 2;
    const int gr = row0 + warp_m * 16 + (lane >> 2);
    const bool ok0 = gr < n, ok1 = gr + 8 < n;
    const float* Xr0 = X + (size_t)gr * 128 + (lane & 3) * 2;
    const float* Xr1 = Xr0 + 8 * 128;
    const int nrowb = warp_n * 64 + ((lane >> 4) & 1) * 8 + (lane & 7);
    const int bkh = (lane >> 3) & 1;

    float acc[8][4];
#pragma unroll
    for (int j = 0; j < 8; j++)
#pragma unroll
        for (int c = 0; c < 4; c++) acc[j][c] = 0.f;

    float2 raw[4];
    raw[0] = ok0 ? *(const float2*)Xr0 : make_float2(0.f, 0.f);
    raw[1] = ok1 ? *(const float2*)Xr1 : make_float2(0.f, 0.f);
    raw[2] = ok0 ? *(const float2*)(Xr0 + 8) : make_float2(0.f, 0.f);
    raw[3] = ok1 ? *(const float2*)(Xr1 + 8) : make_float2(0.f, 0.f);

    CP_WAIT0();
    __syncthreads();

#pragma unroll
    for (int ks = 0; ks < 8; ks++) {
        float2 nxt[4];
        if (ks < 7) {
            const float* p0 = Xr0 + (ks + 1) * 16;
            const float* p1 = Xr1 + (ks + 1) * 16;
            nxt[0] = ok0 ? *(const float2*)p0 : make_float2(0.f, 0.f);
            nxt[1] = ok1 ? *(const float2*)p1 : make_float2(0.f, 0.f);
            nxt[2] = ok0 ? *(const float2*)(p0 + 8) : make_float2(0.f, 0.f);
            nxt[3] = ok1 ? *(const float2*)(p1 + 8) : make_float2(0.f, 0.f);
        }
        u32 ahi[4], alo[4];
#pragma unroll
        for (int q = 0; q < 4; q++) {
            u32 h = pack_bf16x2(raw[q].x, raw[q].y);
            ahi[q] = h;
            float h0 = __uint_as_float(h << 16);
            float h1 = __uint_as_float(h & 0xffff0000u);
            alo[q] = pack_bf16x2(raw[q].x - h0, raw[q].y - h1);
        }
#pragma unroll
        for (int jj = 0; jj < 4; jj++) {
            int r = nrowb + jj * 16;
            u32 off = (u32)(r * 256 + ((((ks * 2 + bkh) ^ (r & 7)) & 15) << 4));
            u32 bh[4], bl[4];
            ldmx4(bh[0], bh[1], bh[2], bh[3], sb + SB_HI + off);
            ldmx4(bl[0], bl[1], bl[2], bl[3], sb + SB_LO + off);
            mma_bf16(acc[jj * 2], ahi, bh);
            mma_bf16(acc[jj * 2], alo, bh);
            mma_bf16(acc[jj * 2], ahi, bl);
            mma_bf16(acc[jj * 2 + 1], ahi, bh + 2);
            mma_bf16(acc[jj * 2 + 1], alo, bh + 2);
            mma_bf16(acc[jj * 2 + 1], ahi, bl + 2);
        }
#pragma unroll
        for (int q = 0; q < 4; q++) raw[q] = nxt[q];
    }

    const int cwb = cb0 + warp_n * 64;
    float* OUT = (cwb < M) ? XL : XR;
    const int cof = (cwb < M) ? cwb : cwb - M;
    const int r0 = row0 + warp_m * 16 + (lane >> 2);
#pragma unroll
    for (int j = 0; j < 8; j++) {
        int c = cof + j * 8 + (lane & 3) * 2;
        if (r0 < n)
            *(float2*)&OUT[(size_t)r0 * M + c] = make_float2(acc[j][0], acc[j][1]);
        if (r0 + 8 < n)
            *(float2*)&OUT[(size_t)(r0 + 8) * M + c] = make_float2(acc[j][2], acc[j][3]);
    }
}

// ---------------- CSR build ----------------
__global__ void k_hist(const int* __restrict__ tgt, int* cnt, int e) {
    int i = blockIdx.x * blockDim.x + threadIdx.x;
    if (i < e) atomicAdd(&cnt[tgt[i]], 1);
}

__global__ void k_scanA(const int* __restrict__ counts, int* __restrict__ lscan,
                        int* __restrict__ bsum, int n) {
    __shared__ int wsum[16];
    const int tid = threadIdx.x, lane = tid & 31, wid = tid >> 5;
    const int i = blockIdx.x * SCHUNK + tid;
    int v = (i < n) ? (counts[i] + 1) : 0;
    int incl = v;
#pragma unroll
    for (int off = 1; off < 32; off <<= 1) {
        int t = __shfl_up_sync(0xffffffffu, incl, off);
        if (lane >= off) incl += t;
    }
    if (lane == 31) wsum[wid] = incl;
    __syncthreads();
    if (tid < 16) {
        int w = wsum[tid];
        int s = w;
#pragma unroll
        for (int off = 1; off < 16; off <<= 1) {
            int t = __shfl_up_sync(0xffffu, s, off);
            if (tid >= off) s += t;
        }
        wsum[tid] = s - w;
    }
    __syncthreads();
    incl += wsum[wid];
    if (i < n) lscan[i] = incl;
    if (tid == SCHUNK - 1) bsum[blockIdx.x] = incl;
}

__global__ void k_scanB(int* bsum, int nb, float* out, float* gcnt) {
    if (blockIdx.x == 0) {
        __shared__ int wsum[4];
        const int tid = threadIdx.x, lane = tid & 31, wid = tid >> 5;
        if (tid < 128) {
            int v = (tid < nb) ? bsum[tid] : 0;
            int incl = v;
#pragma unroll
            for (int off = 1; off < 32; off <<= 1) {
                int t = __shfl_up_sync(0xffffffffu, incl, off);
                if (lane >= off) incl += t;
            }
            if (lane == 31) wsum[wid] = incl;
            __syncthreads();
            int base = 0;
            for (int w = 0; w < wid; w++) base += wsum[w];
            if (tid < nb) bsum[tid] = base + incl - v;
        }
    } else {
        int i = (blockIdx.x - 1) * 256 + threadIdx.x;
        if (i < GG * 64) out[i] = 0.f;
        if (i < GG) gcnt[i] = 0.f;
    }
}

__global__ void k_scanC(const int* __restrict__ counts, int* __restrict__ cursor,
                        const int* __restrict__ lscan, const int* __restrict__ bsum,
                        int* __restrict__ rowptr, int n) {
    int i = blockIdx.x * blockDim.x + threadIdx.x;
    if (i < n) {
        int incl = bsum[i / SCHUNK] + lscan[i];
        rowptr[i + 1] = incl;
        cursor[i] = incl - (counts[i] + 1);
    }
    if (i == 0) rowptr[0] = 0;
}

__global__ void k_scatter(const int* __restrict__ src, const int* __restrict__ tgt,
                          int* wcur, int* col, int e, int n) {
    int i = blockIdx.x * blockDim.x + threadIdx.x;
    if (i < e) {
        int d = tgt[i];
        int p = atomicAdd(&wcur[d], 1);
        col[p] = src[i];
    } else if (i < e + n) {
        int v = i - e;
        int p = atomicAdd(&wcur[v], 1);
        col[p] = v;
    }
}

__global__ void k_zcnt(int* cnt, int n) {
    int i = blockIdx.x * blockDim.x + threadIdx.x;
    if (i < n) cnt[i] = 0;
}

// ---------------- GATv2 aggregation (fixed-ref softmax, depth-4 gather pipeline) ----
template <int V>
__device__ __forceinline__ void ldrow(float* d, const float* p) {
    if (V == 4) { float4 t = *(const float4*)p; d[0]=t.x; d[1]=t.y; d[2]=t.z; d[3]=t.w; }
    else        { float2 t = *(const float2*)p; d[0]=t.x; d[1]=t.y; }
}

template <int HC, int H>
__global__ void k_gat(const float* __restrict__ XL, const float* __restrict__ XR,
                      const int* __restrict__ rowptr, const int* __restrict__ col,
                      const float* __restrict__ att, const float* __restrict__ bias,
                      float* __restrict__ Y, int n) {
    constexpr int V  = HC / 32;
    constexpr int GW = 32 / H;
    const int lane = threadIdx.x & 31;
    const int node = blockIdx.x * (blockDim.x >> 5) + (threadIdx.x >> 5);
    if (node >= n) return;

    float attv[V], bv[V], xr[V], acc[V];
#pragma unroll
    for (int v = 0; v < V; v++) {
        attv[v] = att[lane * V + v];
        bv[v]   = bias[lane * V + v];
        acc[v]  = 0.f;
    }
    ldrow<V>(xr, XR + (size_t)node * HC + lane * V);

    const int e0 = rowptr[node], e1 = rowptr[node + 1];
    float den = 0.f;

    auto proc = [&](const float* xl) {
        float s = 0.f;
#pragma unroll
        for (int v = 0; v < V; v++) {
            float t = xl[v] + xr[v];
            t = fmaxf(t, 0.2f * t);   // leaky relu
            s = fmaf(attv[v], t, s);
        }
#pragma unroll
        for (int off = GW >> 1; off > 0; off >>= 1)
            s += __shfl_xor_sync(0xffffffffu, s, off);
        float w = __expf(s);
        den += w;
#pragma unroll
        for (int v = 0; v < V; v++) acc[v] = fmaf(w, xl[v], acc[v]);
    };

    const int elast = e1 - 1;
    float nb0[V], nb1[V], nb2[V], nb3[V];
    ldrow<V>(nb0, XL + (size_t)__ldg(&col[e0]) * HC + lane * V);
    ldrow<V>(nb1, XL + (size_t)__ldg(&col[min(e0 + 1, elast)]) * HC + lane * V);
    ldrow<V>(nb2, XL + (size_t)__ldg(&col[min(e0 + 2, elast)]) * HC + lane * V);
    ldrow<V>(nb3, XL + (size_t)__ldg(&col[min(e0 + 3, elast)]) * HC + lane * V);

    int e = e0;
    while (true) {
        float xl[V];
#pragma unroll
        for (int v = 0; v < V; v++) xl[v] = nb0[v];
        ldrow<V>(nb0, XL + (size_t)__ldg(&col[min(e + 4, elast)]) * HC + lane * V);
        proc(xl);
        if (++e >= e1) break;
#pragma unroll
        for (int v = 0; v < V; v++) xl[v] = nb1[v];
        ldrow<V>(nb1, XL + (size_t)__ldg(&col[min(e + 4, elast)]) * HC + lane * V);
        proc(xl);
        if (++e >= e1) break;
#pragma unroll
        for (int v = 0; v < V; v++) xl[v] = nb2[v];
        ldrow<V>(nb2, XL + (size_t)__ldg(&col[min(e + 4, elast)]) * HC + lane * V);
        proc(xl);
        if (++e >= e1) break;
#pragma unroll
        for (int v = 0; v < V; v++) xl[v] = nb3[v];
        ldrow<V>(nb3, XL + (size_t)__ldg(&col[min(e + 4, elast)]) * HC + lane * V);
        proc(xl);
        if (++e >= e1) break;
    }

    float inv = 1.f / den;
    float* yp = Y + (size_t)node * HC + lane * V;
#pragma unroll
    for (int v = 0; v < V; v++) {
        float y = fmaf(acc[v], inv, bv[v]);
        yp[v] = (y > 0.f) ? y : 0.2f * y;
    }
}

// ---------------- global mean pool with fused finalize ----------------
#define PCH 256
__global__ void k_pool2(const float* __restrict__ X, const int* __restrict__ batch,
                        float* out, float* cnt, int n) {
    __shared__ bool s_last;
    const int f = threadIdx.x;
    const int chunk = blockIdx.x * blockDim.y + threadIdx.y;
    const int n0 = chunk * PCH;
    if (n0 < n) {
        const int n1 = min(n, n0 + PCH);
        int curg = __ldg(&batch[n0]);
        float acc = 0.f, c = 0.f;
        for (int node = n0; node < n1; node++) {
            int g = __ldg(&batch[node]);
            if (g != curg) {
                atomicAdd(&out[curg * 64 + f], acc);
                if (f == 0) atomicAdd(&cnt[curg], c);
                acc = 0.f; c = 0.f; curg = g;
            }
            acc += X[(size_t)node * 64 + f];
            c += 1.f;
        }
        atomicAdd(&out[curg * 64 + f], acc);
        if (f == 0) atomicAdd(&cnt[curg], c);
    }
    __threadfence();
    __syncthreads();
    const int tid = threadIdx.y * 64 + threadIdx.x;
    if (tid == 0) {
        u32 t = atomicAdd(&g_poolctr, 1u);
        s_last = (t == gridDim.x - 1);
    }
    __syncthreads();
    if (s_last) {
        for (int i = tid; i < GG * 64; i += 256)
            out[i] /= fmaxf(cnt[i >> 6], 1.f);
        if (tid == 0) g_poolctr = 0;
    }
}

// ---------------- launch ----------------
extern "C" void kernel_launch(void* const* d_in, const int* in_sizes, int n_in,
                              void* d_out, int out_size) {
    const float* x     = (const float*)d_in[0];
    const int*   ei    = (const int*)d_in[1];
    const int*   batch = (const int*)d_in[2];
    const float* Wl0 = (const float*)d_in[3];
    const float* Wr0 = (const float*)d_in[4];
    const float* at0 = (const float*)d_in[5];
    const float* b0  = (const float*)d_in[6];
    const float* Wl1 = (const float*)d_in[7];
    const float* Wr1 = (const float*)d_in[8];
    const float* at1 = (const float*)d_in[9];
    const float* b1  = (const float*)d_in[10];
    const float* Wl2 = (const float*)d_in[11];
    const float* Wr2 = (const float*)d_in[12];
    const float* at2 = (const float*)d_in[13];
    const float* b2  = (const float*)d_in[14];
    float* out = (float*)d_out;

    const int n = in_sizes[2];
    const int e = in_sizes[1] / 2;
    const int* src = ei;
    const int* tgt = ei + e;

    float *pXL, *pXR, *pBA, *pBB, *pcnt;
    int *prow, *ptmp, *pcol, *plscan, *pbsum;
    u16 *pBhi0, *pBlo0, *pBhi1, *pBlo1, *pBhi2, *pBlo2;
    cudaGetSymbolAddress((void**)&pXL, g_XL);
    cudaGetSymbolAddress((void**)&pXR, g_XR);
    cudaGetSymbolAddress((void**)&pBA, g_BA);
    cudaGetSymbolAddress((void**)&pBB, g_BB);
    cudaGetSymbolAddress((void**)&prow, g_rowptr);
    cudaGetSymbolAddress((void**)&ptmp, g_tmp);
    cudaGetSymbolAddress((void**)&pcol, g_col);
    cudaGetSymbolAddress((void**)&plscan, g_lscan);
    cudaGetSymbolAddress((void**)&pbsum, g_bsum);
    cudaGetSymbolAddress((void**)&pcnt, g_cnt);
    cudaGetSymbolAddress((void**)&pBhi0, g_Bhi0);
    cudaGetSymbolAddress((void**)&pBlo0, g_Blo0);
    cudaGetSymbolAddress((void**)&pBhi1, g_Bhi1);
    cudaGetSymbolAddress((void**)&pBlo1, g_Blo1);
    cudaGetSymbolAddress((void**)&pBhi2, g_Bhi2);
    cudaGetSymbolAddress((void**)&pBlo2, g_Blo2);

    cudaFuncSetAttribute(k_gemm_hmma, cudaFuncAttributeMaxDynamicSharedMemorySize, GSMEM);

    const int gx      = (n + 63) / 64;
    const int ablocks = (n + 7) / 8;
    const int nsb     = (n + SCHUNK - 1) / SCHUNK;

    cudaStream_t s;
    cudaStreamCreateWithFlags(&s, cudaStreamNonBlocking);
    cudaEvent_t eFork, eJoin;
    cudaEventCreateWithFlags(&eFork, cudaEventDisableTiming);
    cudaEventCreateWithFlags(&eJoin, cudaEventDisableTiming);

    cudaEventRecord(eFork, 0);
    cudaStreamWaitEvent(s, eFork, 0);

    // ---- side stream: prep for layers 1/2 + CSR build + pool-buffer zeroing
    k_prep12<<<192, 256, 0, s>>>(Wl1, Wr1, Wl2, Wr2, pBhi1, pBlo1, pBhi2, pBlo2);
    k_hist<<<(e + 255) / 256, 256, 0, s>>>(tgt, ptmp, e);
    k_scanA<<<nsb, SCHUNK, 0, s>>>(ptmp, plscan, pbsum, n);
    k_scanB<<<1 + (GG * 64 + 255) / 256, 256, 0, s>>>(pbsum, nsb, out, pcnt);
    k_scanC<<<(n + 255) / 256, 256, 0, s>>>(ptmp, ptmp, plscan, pbsum, prow, n);
    k_scatter<<<(e + n + 255) / 256, 256, 0, s>>>(src, tgt, ptmp, pcol, e, n);
    k_zcnt<<<(n + 255) / 256, 256, 0, s>>>(ptmp, n);
    cudaEventRecord(eJoin, s);

    // ---- main stream: layer-0 prep + GEMM
    k_prep0<<<128, 256>>>(Wl0, Wr0, pBhi0, pBlo0);
    k_gemm_hmma<<<dim3(gx, 2), 256, GSMEM>>>(x, pBhi0, pBlo0, pXL, pXR, n, 128);

    cudaStreamWaitEvent(0, eJoin, 0);

    // layer 0 aggregate
    k_gat<128, 4><<<ablocks, 256>>>(pXL, pXR, prow, pcol, at0, b0, pBA, n);

    // layer 1
    k_gemm_hmma<<<dim3(gx, 2), 256, GSMEM>>>(pBA, pBhi1, pBlo1, pXL, pXR, n, 128);
    k_gat<128, 4><<<ablocks, 256>>>(pXL, pXR, prow, pcol, at1, b1, pBB, n);

    // layer 2 (1 head x 64)
    k_gemm_hmma<<<dim3(gx, 1), 256, GSMEM>>>(pBB, pBhi2, pBlo2, pXL, pXR, n, 64);
    k_gat<64, 1><<<ablocks, 256>>>(pXL, pXR, prow, pcol, at2, b2, pBA, n);

    // global mean pool (finalize fused)
    {
        dim3 blk(64, 4);
        int pblocks = (n + PCH * 4 - 1) / (PCH * 4);
        k_pool2<<<pblocks, blk>>>(pBA, batch, out, pcnt, n);
    }
}

// round 15
// speedup vs baseline: 1.1112x; 1.0493x over previous
#include <cuda_runtime.h>
#include <cuda_bf16.h>
#include <math.h>

#define NN 50000
#define EE 800000
#define GG 64
#define ETOT (EE + NN)
#define SCHUNK 512

typedef unsigned long long ull;
typedef unsigned int u32;
typedef unsigned short u16;

// ---------------- static device scratch ----------------
__device__ float g_XL[NN * 128];
__device__ float g_XR[NN * 128];
__device__ float g_BA[NN * 128];
__device__ float g_BB[NN * 128];
__device__ int   g_rowptr[NN + 1];
__device__ int   g_tmp[NN];
__device__ int   g_lscan[NN];
__device__ int   g_bsum[256];
__device__ int   g_col[ETOT];
__device__ float g_cnt[GG];
__device__ u32   g_poolctr;
__device__ u16   g_Bhi0[256 * 128];
__device__ u16   g_Blo0[256 * 128];
__device__ u16   g_Bhi1[256 * 128];
__device__ u16   g_Blo1[256 * 128];
__device__ u16   g_Bhi2[128 * 128];
__device__ u16   g_Blo2[128 * 128];

// ---------------- helpers ----------------
__device__ __forceinline__ u32 smem_u32(const void* p) {
    u32 a;
    asm("{ .reg .u64 t; cvta.to.shared.u64 t, %1; cvt.u32.u64 %0, t; }" : "=r"(a) : "l"(p));
    return a;
}

__device__ __forceinline__ u32 pack_bf16x2(float lo, float hi) {
    u32 r;
    asm("cvt.rn.bf16x2.f32 %0, %1, %2;" : "=r"(r) : "f"(hi), "f"(lo));
    return r;
}

__device__ __forceinline__ u32 swz_off(int r, int k) {
    int chunk = k >> 3;
    return (u32)(r * 256 + (((chunk ^ (r & 7)) & 15) << 4) + (k & 7) * 2);
}

__device__ __forceinline__ void ldmx4(u32& r0, u32& r1, u32& r2, u32& r3, u32 addr) {
    asm volatile("ldmatrix.sync.aligned.m8n8.x4.shared.b16 {%0,%1,%2,%3}, [%4];"
                 : "=r"(r0), "=r"(r1), "=r"(r2), "=r"(r3) : "r"(addr));
}

__device__ __forceinline__ void mma_bf16(float* c, const u32* a, const u32* b) {
    asm volatile("mma.sync.aligned.m16n8k16.row.col.f32.bf16.bf16.f32 "
                 "{%0,%1,%2,%3}, {%4,%5,%6,%7}, {%8,%9}, {%0,%1,%2,%3};"
                 : "+f"(c[0]), "+f"(c[1]), "+f"(c[2]), "+f"(c[3])
                 : "r"(a[0]), "r"(a[1]), "r"(a[2]), "r"(a[3]), "r"(b[0]), "r"(b[1]));
}

__device__ __forceinline__ void cp16(u32 s, const void* g) {
    asm volatile("{ .reg .u64 t; cvta.to.global.u64 t, %1; "
                 "cp.async.cg.shared.global [%0], [t], 16; }" :: "r"(s), "l"(g));
}
#define CP_COMMIT() asm volatile("cp.async.commit_group;" ::: "memory")
#define CP_WAIT0()  asm volatile("cp.async.wait_group 0;" ::: "memory")

// ---------------- weight prep ----------------
__device__ __forceinline__ void prep_one(const float* __restrict__ Wl,
                                         const float* __restrict__ Wr,
                                         u16* __restrict__ Bhi, u16* __restrict__ Blo,
                                         int M, int i) {
    int r = i >> 7, k = i & 127;
    float v = (r < M) ? Wl[k * M + r] : Wr[k * M + r - M];
    __nv_bfloat16 h = __float2bfloat16(v);
    float hf = __bfloat162float(h);
    __nv_bfloat16 l = __float2bfloat16(v - hf);
    u32 off = swz_off(r, k) >> 1;
    Bhi[off] = *(u16*)&h;
    Blo[off] = *(u16*)&l;
}

__global__ void k_prep0(const float* Wl0, const float* Wr0, u16* Bhi0, u16* Blo0) {
    int i = blockIdx.x * blockDim.x + threadIdx.x;
    if (i < 32768) prep_one(Wl0, Wr0, Bhi0, Blo0, 128, i);
}

__global__ void k_prep12(const float* Wl1, const float* Wr1,
                         const float* Wl2, const float* Wr2,
                         u16* Bhi1, u16* Blo1, u16* Bhi2, u16* Blo2) {
    int i = blockIdx.x * blockDim.x + threadIdx.x;
    if (i < 32768)      prep_one(Wl1, Wr1, Bhi1, Blo1, 128, i);
    else if (i < 49152) prep_one(Wl2, Wr2, Bhi2, Blo2, 64, i - 32768);
}

// ---------------- HMMA dual GEMM: 64 rows x 128 cols, warp tile 16x64 ----------------
#define SB_HI 0
#define SB_LO 32768
#define GSMEM 65536

__global__ __launch_bounds__(256, 2)
void k_gemm_hmma(const float* __restrict__ X, const u16* __restrict__ Bimg_hi,
                 const u16* __restrict__ Bimg_lo, float* __restrict__ XL,
                 float* __restrict__ XR, int n, int M) {
    extern __shared__ char smem[];
    const u32 sb = smem_u32(smem);
    const int tid = threadIdx.x, wid = tid >> 5, lane = tid & 31;
    const int row0 = blockIdx.x * 64;
    const int cb0 = blockIdx.y * 128;

    {
        const char* bh = (const char*)(Bimg_hi + (size_t)cb0 * 128);
        const char* bl = (const char*)(Bimg_lo + (size_t)cb0 * 128);
        for (int i = tid * 16; i < 32768; i += 256 * 16) {
            cp16(sb + SB_HI + i, bh + i);
            cp16(sb + SB_LO + i, bl + i);
        }
        CP_COMMIT();
    }

    const int warp_m = wid & 3;
    const int warp_n = wid >> 2;
    const int gr = row0 + warp_m * 16 + (lane >> 2);
    const bool ok0 = gr < n, ok1 = gr + 8 < n;
    const float* Xr0 = X + (size_t)gr * 128 + (lane & 3) * 2;
    const float* Xr1 = Xr0 + 8 * 128;
    const int nrowb = warp_n * 64 + ((lane >> 4) & 1) * 8 + (lane & 7);
    const int bkh = (lane >> 3) & 1;

    float acc[8][4];
#pragma unroll
    for (int j = 0; j < 8; j++)
#pragma unroll
        for (int c = 0; c < 4; c++) acc[j][c] = 0.f;

    float2 raw[4];
    raw[0] = ok0 ? *(const float2*)Xr0 : make_float2(0.f, 0.f);
    raw[1] = ok1 ? *(const float2*)Xr1 : make_float2(0.f, 0.f);
    raw[2] = ok0 ? *(const float2*)(Xr0 + 8) : make_float2(0.f, 0.f);
    raw[3] = ok1 ? *(const float2*)(Xr1 + 8) : make_float2(0.f, 0.f);

    CP_WAIT0();
    __syncthreads();

#pragma unroll
    for (int ks = 0; ks < 8; ks++) {
        float2 nxt[4];
        if (ks < 7) {
            const float* p0 = Xr0 + (ks + 1) * 16;
            const float* p1 = Xr1 + (ks + 1) * 16;
            nxt[0] = ok0 ? *(const float2*)p0 : make_float2(0.f, 0.f);
            nxt[1] = ok1 ? *(const float2*)p1 : make_float2(0.f, 0.f);
            nxt[2] = ok0 ? *(const float2*)(p0 + 8) : make_float2(0.f, 0.f);
            nxt[3] = ok1 ? *(const float2*)(p1 + 8) : make_float2(0.f, 0.f);
        }
        u32 ahi[4], alo[4];
#pragma unroll
        for (int q = 0; q < 4; q++) {
            u32 h = pack_bf16x2(raw[q].x, raw[q].y);
            ahi[q] = h;
            float h0 = __uint_as_float(h << 16);
            float h1 = __uint_as_float(h & 0xffff0000u);
            alo[q] = pack_bf16x2(raw[q].x - h0, raw[q].y - h1);
        }
#pragma unroll
        for (int jj = 0; jj < 4; jj++) {
            int r = nrowb + jj * 16;
            u32 off = (u32)(r * 256 + ((((ks * 2 + bkh) ^ (r & 7)) & 15) << 4));
            u32 bh[4], bl[4];
            ldmx4(bh[0], bh[1], bh[2], bh[3], sb + SB_HI + off);
            ldmx4(bl[0], bl[1], bl[2], bl[3], sb + SB_LO + off);
            mma_bf16(acc[jj * 2], ahi, bh);
            mma_bf16(acc[jj * 2], alo, bh);
            mma_bf16(acc[jj * 2], ahi, bl);
            mma_bf16(acc[jj * 2 + 1], ahi, bh + 2);
            mma_bf16(acc[jj * 2 + 1], alo, bh + 2);
            mma_bf16(acc[jj * 2 + 1], ahi, bl + 2);
        }
#pragma unroll
        for (int q = 0; q < 4; q++) raw[q] = nxt[q];
    }

    const int cwb = cb0 + warp_n * 64;
    float* OUT = (cwb < M) ? XL : XR;
    const int cof = (cwb < M) ? cwb : cwb - M;
    const int r0 = row0 + warp_m * 16 + (lane >> 2);
#pragma unroll
    for (int j = 0; j < 8; j++) {
        int c = cof + j * 8 + (lane & 3) * 2;
        if (r0 < n)
            *(float2*)&OUT[(size_t)r0 * M + c] = make_float2(acc[j][0], acc[j][1]);
        if (r0 + 8 < n)
            *(float2*)&OUT[(size_t)(r0 + 8) * M + c] = make_float2(acc[j][2], acc[j][3]);
    }
}

// ---------------- CSR build ----------------
__global__ void k_hist(const int* __restrict__ tgt, int* cnt, int e) {
    int i = blockIdx.x * blockDim.x + threadIdx.x;
    if (i < e) atomicAdd(&cnt[tgt[i]], 1);
}

__global__ void k_scanA(const int* __restrict__ counts, int* __restrict__ lscan,
                        int* __restrict__ bsum, int n) {
    __shared__ int wsum[16];
    const int tid = threadIdx.x, lane = tid & 31, wid = tid >> 5;
    const int i = blockIdx.x * SCHUNK + tid;
    int v = (i < n) ? (counts[i] + 1) : 0;
    int incl = v;
#pragma unroll
    for (int off = 1; off < 32; off <<= 1) {
        int t = __shfl_up_sync(0xffffffffu, incl, off);
        if (lane >= off) incl += t;
    }
    if (lane == 31) wsum[wid] = incl;
    __syncthreads();
    if (tid < 16) {
        int w = wsum[tid];
        int s = w;
#pragma unroll
        for (int off = 1; off < 16; off <<= 1) {
            int t = __shfl_up_sync(0xffffu, s, off);
            if (tid >= off) s += t;
        }
        wsum[tid] = s - w;
    }
    __syncthreads();
    incl += wsum[wid];
    if (i < n) lscan[i] = incl;
    if (tid == SCHUNK - 1) bsum[blockIdx.x] = incl;
}

__global__ void k_scanB(int* bsum, int nb, float* out, float* gcnt) {
    if (blockIdx.x == 0) {
        __shared__ int wsum[4];
        const int tid = threadIdx.x, lane = tid & 31, wid = tid >> 5;
        if (tid < 128) {
            int v = (tid < nb) ? bsum[tid] : 0;
            int incl = v;
#pragma unroll
            for (int off = 1; off < 32; off <<= 1) {
                int t = __shfl_up_sync(0xffffffffu, incl, off);
                if (lane >= off) incl += t;
            }
            if (lane == 31) wsum[wid] = incl;
            __syncthreads();
            int base = 0;
            for (int w = 0; w < wid; w++) base += wsum[w];
            if (tid < nb) bsum[tid] = base + incl - v;
        }
    } else {
        int i = (blockIdx.x - 1) * 256 + threadIdx.x;
        if (i < GG * 64) out[i] = 0.f;
        if (i < GG) gcnt[i] = 0.f;
    }
}

__global__ void k_scanC(const int* __restrict__ counts, int* __restrict__ cursor,
                        const int* __restrict__ lscan, const int* __restrict__ bsum,
                        int* __restrict__ rowptr, int n) {
    int i = blockIdx.x * blockDim.x + threadIdx.x;
    if (i < n) {
        int incl = bsum[i / SCHUNK] + lscan[i];
        rowptr[i + 1] = incl;
        cursor[i] = incl - (counts[i] + 1);
    }
    if (i == 0) rowptr[0] = 0;
}

__global__ void k_scatter(const int* __restrict__ src, const int* __restrict__ tgt,
                          int* wcur, int* col, int e, int n) {
    int i = blockIdx.x * blockDim.x + threadIdx.x;
    if (i < e) {
        int d = tgt[i];
        int p = atomicAdd(&wcur[d], 1);
        col[p] = src[i];
    } else if (i < e + n) {
        int v = i - e;
        int p = atomicAdd(&wcur[v], 1);
        col[p] = v;
    }
}

__global__ void k_zcnt(int* cnt, int n) {
    int i = blockIdx.x * blockDim.x + threadIdx.x;
    if (i < n) cnt[i] = 0;
}

// ---------------- GATv2 aggregation: pair loop, independent chains per pair ----------
template <int V>
__device__ __forceinline__ void ldrow(float* d, const float* p) {
    if (V == 4) { float4 t = *(const float4*)p; d[0]=t.x; d[1]=t.y; d[2]=t.z; d[3]=t.w; }
    else        { float2 t = *(const float2*)p; d[0]=t.x; d[1]=t.y; }
}

template <int HC, int H>
__global__ void k_gat(const float* __restrict__ XL, const float* __restrict__ XR,
                      const int* __restrict__ rowptr, const int* __restrict__ col,
                      const float* __restrict__ att, const float* __restrict__ bias,
                      float* __restrict__ Y, int n) {
    constexpr int V  = HC / 32;
    constexpr int GW = 32 / H;
    const int lane = threadIdx.x & 31;
    const int node = blockIdx.x * (blockDim.x >> 5) + (threadIdx.x >> 5);
    if (node >= n) return;

    float attv[V], bv[V], xr[V], acc[V];
#pragma unroll
    for (int v = 0; v < V; v++) {
        attv[v] = att[lane * V + v];
        bv[v]   = bias[lane * V + v];
        acc[v]  = 0.f;
    }
    ldrow<V>(xr, XR + (size_t)node * HC + lane * V);

    const int e0 = rowptr[node], e1 = rowptr[node + 1];
    const int elast = e1 - 1;
    float den = 0.f;

    float nb0[V], nb1[V];
    ldrow<V>(nb0, XL + (size_t)__ldg(&col[e0]) * HC + lane * V);
    ldrow<V>(nb1, XL + (size_t)__ldg(&col[min(e0 + 1, elast)]) * HC + lane * V);

    int e = e0;
    // pair loop: two independent edge chains per iteration, no breaks between them
    while (e + 1 < e1) {
        float xl0[V], xl1[V];
#pragma unroll
        for (int v = 0; v < V; v++) { xl0[v] = nb0[v]; xl1[v] = nb1[v]; }
        ldrow<V>(nb0, XL + (size_t)__ldg(&col[min(e + 2, elast)]) * HC + lane * V);
        ldrow<V>(nb1, XL + (size_t)__ldg(&col[min(e + 3, elast)]) * HC + lane * V);

        float s0 = 0.f, s1 = 0.f;
#pragma unroll
        for (int v = 0; v < V; v++) {
            float t0 = xl0[v] + xr[v];
            float t1 = xl1[v] + xr[v];
            t0 = fmaxf(t0, 0.2f * t0);
            t1 = fmaxf(t1, 0.2f * t1);
            s0 = fmaf(attv[v], t0, s0);
            s1 = fmaf(attv[v], t1, s1);
        }
#pragma unroll
        for (int off = GW >> 1; off > 0; off >>= 1) {
            s0 += __shfl_xor_sync(0xffffffffu, s0, off);
            s1 += __shfl_xor_sync(0xffffffffu, s1, off);
        }
        float w0 = __expf(s0);
        float w1 = __expf(s1);
        den += w0 + w1;
#pragma unroll
        for (int v = 0; v < V; v++)
            acc[v] = fmaf(w1, xl1[v], fmaf(w0, xl0[v], acc[v]));
        e += 2;
    }
    // tail (odd degree)
    if (e < e1) {
        float s = 0.f;
#pragma unroll
        for (int v = 0; v < V; v++) {
            float t = nb0[v] + xr[v];
            t = fmaxf(t, 0.2f * t);
            s = fmaf(attv[v], t, s);
        }
#pragma unroll
        for (int off = GW >> 1; off > 0; off >>= 1)
            s += __shfl_xor_sync(0xffffffffu, s, off);
        float w = __expf(s);
        den += w;
#pragma unroll
        for (int v = 0; v < V; v++) acc[v] = fmaf(w, nb0[v], acc[v]);
    }

    float inv = 1.f / den;
    float* yp = Y + (size_t)node * HC + lane * V;
#pragma unroll
    for (int v = 0; v < V; v++) {
        float y = fmaf(acc[v], inv, bv[v]);
        yp[v] = (y > 0.f) ? y : 0.2f * y;
    }
}

// ---------------- global mean pool with fused finalize ----------------
#define PCH 256
__global__ void k_pool2(const float* __restrict__ X, const int* __restrict__ batch,
                        float* out, float* cnt, int n) {
    __shared__ bool s_last;
    const int f = threadIdx.x;
    const int chunk = blockIdx.x * blockDim.y + threadIdx.y;
    const int n0 = chunk * PCH;
    if (n0 < n) {
        const int n1 = min(n, n0 + PCH);
        int curg = __ldg(&batch[n0]);
        float acc = 0.f, c = 0.f;
        for (int node = n0; node < n1; node++) {
            int g = __ldg(&batch[node]);
            if (g != curg) {
                atomicAdd(&out[curg * 64 + f], acc);
                if (f == 0) atomicAdd(&cnt[curg], c);
                acc = 0.f; c = 0.f; curg = g;
            }
            acc += X[(size_t)node * 64 + f];
            c += 1.f;
        }
        atomicAdd(&out[curg * 64 + f], acc);
        if (f == 0) atomicAdd(&cnt[curg], c);
    }
    __threadfence();
    __syncthreads();
    const int tid = threadIdx.y * 64 + threadIdx.x;
    if (tid == 0) {
        u32 t = atomicAdd(&g_poolctr, 1u);
        s_last = (t == gridDim.x - 1);
    }
    __syncthreads();
    if (s_last) {
        for (int i = tid; i < GG * 64; i += 256)
            out[i] /= fmaxf(cnt[i >> 6], 1.f);
        if (tid == 0) g_poolctr = 0;
    }
}

// ---------------- launch ----------------
extern "C" void kernel_launch(void* const* d_in, const int* in_sizes, int n_in,
                              void* d_out, int out_size) {
    const float* x     = (const float*)d_in[0];
    const int*   ei    = (const int*)d_in[1];
    const int*   batch = (const int*)d_in[2];
    const float* Wl0 = (const float*)d_in[3];
    const float* Wr0 = (const float*)d_in[4];
    const float* at0 = (const float*)d_in[5];
    const float* b0  = (const float*)d_in[6];
    const float* Wl1 = (const float*)d_in[7];
    const float* Wr1 = (const float*)d_in[8];
    const float* at1 = (const float*)d_in[9];
    const float* b1  = (const float*)d_in[10];
    const float* Wl2 = (const float*)d_in[11];
    const float* Wr2 = (const float*)d_in[12];
    const float* at2 = (const float*)d_in[13];
    const float* b2  = (const float*)d_in[14];
    float* out = (float*)d_out;

    const int n = in_sizes[2];
    const int e = in_sizes[1] / 2;
    const int* src = ei;
    const int* tgt = ei + e;

    float *pXL, *pXR, *pBA, *pBB, *pcnt;
    int *prow, *ptmp, *pcol, *plscan, *pbsum;
    u16 *pBhi0, *pBlo0, *pBhi1, *pBlo1, *pBhi2, *pBlo2;
    cudaGetSymbolAddress((void**)&pXL, g_XL);
    cudaGetSymbolAddress((void**)&pXR, g_XR);
    cudaGetSymbolAddress((void**)&pBA, g_BA);
    cudaGetSymbolAddress((void**)&pBB, g_BB);
    cudaGetSymbolAddress((void**)&prow, g_rowptr);
    cudaGetSymbolAddress((void**)&ptmp, g_tmp);
    cudaGetSymbolAddress((void**)&pcol, g_col);
    cudaGetSymbolAddress((void**)&plscan, g_lscan);
    cudaGetSymbolAddress((void**)&pbsum, g_bsum);
    cudaGetSymbolAddress((void**)&pcnt, g_cnt);
    cudaGetSymbolAddress((void**)&pBhi0, g_Bhi0);
    cudaGetSymbolAddress((void**)&pBlo0, g_Blo0);
    cudaGetSymbolAddress((void**)&pBhi1, g_Bhi1);
    cudaGetSymbolAddress((void**)&pBlo1, g_Blo1);
    cudaGetSymbolAddress((void**)&pBhi2, g_Bhi2);
    cudaGetSymbolAddress((void**)&pBlo2, g_Blo2);

    cudaFuncSetAttribute(k_gemm_hmma, cudaFuncAttributeMaxDynamicSharedMemorySize, GSMEM);

    const int gx      = (n + 63) / 64;
    const int ablocks = (n + 7) / 8;
    const int nsb     = (n + SCHUNK - 1) / SCHUNK;

    cudaStream_t s;
    cudaStreamCreateWithFlags(&s, cudaStreamNonBlocking);
    cudaEvent_t eFork, eJoin;
    cudaEventCreateWithFlags(&eFork, cudaEventDisableTiming);
    cudaEventCreateWithFlags(&eJoin, cudaEventDisableTiming);

    cudaEventRecord(eFork, 0);
    cudaStreamWaitEvent(s, eFork, 0);

    // ---- side stream: prep for layers 1/2 + CSR build + pool-buffer zeroing
    k_prep12<<<192, 256, 0, s>>>(Wl1, Wr1, Wl2, Wr2, pBhi1, pBlo1, pBhi2, pBlo2);
    k_hist<<<(e + 255) / 256, 256, 0, s>>>(tgt, ptmp, e);
    k_scanA<<<nsb, SCHUNK, 0, s>>>(ptmp, plscan, pbsum, n);
    k_scanB<<<1 + (GG * 64 + 255) / 256, 256, 0, s>>>(pbsum, nsb, out, pcnt);
    k_scanC<<<(n + 255) / 256, 256, 0, s>>>(ptmp, ptmp, plscan, pbsum, prow, n);
    k_scatter<<<(e + n + 255) / 256, 256, 0, s>>>(src, tgt, ptmp, pcol, e, n);
    k_zcnt<<<(n + 255) / 256, 256, 0, s>>>(ptmp, n);
    cudaEventRecord(eJoin, s);

    // ---- main stream: layer-0 prep + GEMM
    k_prep0<<<128, 256>>>(Wl0, Wr0, pBhi0, pBlo0);
    k_gemm_hmma<<<dim3(gx, 2), 256, GSMEM>>>(x, pBhi0, pBlo0, pXL, pXR, n, 128);

    cudaStreamWaitEvent(0, eJoin, 0);

    // layer 0 aggregate
    k_gat<128, 4><<<ablocks, 256>>>(pXL, pXR, prow, pcol, at0, b0, pBA, n);

    // layer 1
    k_gemm_hmma<<<dim3(gx, 2), 256, GSMEM>>>(pBA, pBhi1, pBlo1, pXL, pXR, n, 128);
    k_gat<128, 4><<<ablocks, 256>>>(pXL, pXR, prow, pcol, at1, b1, pBB, n);

    // layer 2 (1 head x 64)
    k_gemm_hmma<<<dim3(gx, 1), 256, GSMEM>>>(pBB, pBhi2, pBlo2, pXL, pXR, n, 64);
    k_gat<64, 1><<<ablocks, 256>>>(pXL, pXR, prow, pcol, at2, b2, pBA, n);

    // global mean pool (finalize fused)
    {
        dim3 blk(64, 4);
        int pblocks = (n + PCH * 4 - 1) / (PCH * 4);
        k_pool2<<<pblocks, blk>>>(pBA, batch, out, pcnt, n);
    }
}